// round 5
// baseline (speedup 1.0000x reference)
#include <cuda_runtime.h>

// image [8,512,512,32] f32, slic [8,512,512,1] i32 in [1,256]
// out [8,256,32] f32 = segment_sum(image) / segment_count_nonzero(image) per channel.

#define BATCH 8
#define HW    (512*512)
#define C     32
#define S     256
#define CS    33                 // skewed stride: bank = (s + c) mod 32
#define BLOCKS_PER_IMG 37        // 37*8 = 296 blocks = 2 per SM
#define THREADS 1024             // 32 warps per block, warp-per-pixel
#define WARPS  (THREADS / 32)
#define PSTRIDE (BLOCKS_PER_IMG * WARPS)   // 1184 pixels per grid-x sweep

// Scratch (zero-initialized at module load; finalize restores zeros each call).
__device__ float g_sums[BATCH * S * C];   // 256 KB
__device__ float g_zero[BATCH * S * C];   // zero-value corrections (rarely touched)
__device__ float g_pix [BATCH * S];       // pixel count per (image, segment)

// ---------------------------------------------------------------------------
// Kernel 1: privatized scatter-reduce, warp-per-pixel.
//   lane = channel. Shared index s*33 + c -> bank (s + c) mod 32: one segment
//   per warp instruction means all 32 lanes hit 32 DISTINCT banks — shared
//   atomics are conflict-free by construction (vs E[2.17x] with the old
//   4-pixel layout, whose mod-4 cosets collided with P=1/4 per pixel pair).
//   Image loads: 32 consecutive floats per warp = one coalesced 128B line.
//   Counts: 1 pixel-count atomic per pixel (lane 0) + per-channel zero
//   correction in global (exact count_nonzero; ~never fires for gaussian).
// ---------------------------------------------------------------------------
__global__ void __launch_bounds__(THREADS, 2)
seg_accum(const float* __restrict__ img, const int* __restrict__ slic) {
    __shared__ float s_sum[S * CS];  // 33.8 KB, skewed
    __shared__ float s_pix[S];       // 1 KB

    const int b    = blockIdx.y;
    const int warp = threadIdx.x >> 5;
    const int lane = threadIdx.x & 31;

    for (int i = threadIdx.x; i < S * CS; i += THREADS) s_sum[i] = 0.0f;
    if (threadIdx.x < S) s_pix[threadIdx.x] = 0.0f;
    __syncthreads();

    const float* __restrict__ imgb  = img  + (size_t)b * HW * C;
    const int*   __restrict__ slicb = slic + (size_t)b * HW;
    float* __restrict__ gz = g_zero + (size_t)b * S * C;

    const int base = blockIdx.x * WARPS + warp;

    // Process 4 pixels per iteration: batch the loads up front for MLP,
    // then issue the (independent) atomic rounds.
    for (int p0 = base; p0 < HW; p0 += 4 * PSTRIDE) {
        int   seg[4];
        float val[4];
        #pragma unroll
        for (int j = 0; j < 4; j++) {
            const int p = p0 + j * PSTRIDE;
            if (p < HW) {
                seg[j] = slicb[p] - 1;                       // broadcast load
                val[j] = imgb[(size_t)p * C + lane];         // coalesced 128B
            } else {
                seg[j] = -1;
                val[j] = 0.0f;
            }
        }
        #pragma unroll
        for (int j = 0; j < 4; j++) {
            if (seg[j] >= 0) {
                atomicAdd(&s_sum[seg[j] * CS + lane], val[j]);   // conflict-free
                if (lane == 0) atomicAdd(&s_pix[seg[j]], 1.0f);
                if (val[j] == 0.0f)                              // exact count_nonzero
                    atomicAdd(&gz[seg[j] * C + lane], 1.0f);
            }
        }
    }
    __syncthreads();

    // Flush block-private accumulators to global (de-skew on the way out).
    float* __restrict__ gs = g_sums + (size_t)b * S * C;
    for (int i = threadIdx.x; i < S * C; i += THREADS) {
        const int s = i >> 5, c = i & 31;
        atomicAdd(&gs[i], s_sum[s * CS + c]);
    }
    if (threadIdx.x < S)
        atomicAdd(&g_pix[b * S + threadIdx.x], s_pix[threadIdx.x]);
}

// ---------------------------------------------------------------------------
// Kernel 2: out = sum / (pixel_count - zero_count), then re-zero the scratch
// so the next graph replay starts clean (removes the zero_scratch launch).
// Safe: the 32 g_pix readers and the single writer are the SAME warp, and
// the warp-wide load instruction precedes the lane-0 store in program order.
// ---------------------------------------------------------------------------
__global__ void finalize(float* __restrict__ out) {
    int i = blockIdx.x * blockDim.x + threadIdx.x;
    if (i < BATCH * S * C) {
        float cnt = g_pix[i >> 5] - g_zero[i];
        out[i] = g_sums[i] / cnt;
        g_sums[i] = 0.0f;
        g_zero[i] = 0.0f;
        if ((i & 31) == 0) g_pix[i >> 5] = 0.0f;
    }
}

// ---------------------------------------------------------------------------
// Entry point (graph-capturable: kernel launches only, no sync, no alloc).
// ---------------------------------------------------------------------------
extern "C" void kernel_launch(void* const* d_in, const int* in_sizes, int n_in,
                              void* d_out, int out_size) {
    const float* img  = (const float*)d_in[0];   // image, 67108864 f32
    const int*   slic = (const int*)  d_in[1];   // slic,   2097152 i32
    float*       out  = (float*)d_out;           // 65536 f32

    (void)in_sizes; (void)n_in; (void)out_size;

    dim3 grid(BLOCKS_PER_IMG, BATCH);
    seg_accum<<<grid, THREADS>>>(img, slic);

    finalize<<<(BATCH * S * C + 255) / 256, 256>>>(out);
}

// round 6
// speedup vs baseline: 1.3135x; 1.3135x over previous
#include <cuda_runtime.h>

// image [8,512,512,32] f32, slic [8,512,512,1] i32 in [1,256]
// out [8,256,32] f32 = segment_sum(image) / segment_count_nonzero(image) per channel.

#define BATCH 8
#define HW    (512*512)
#define C     32
#define S     256
#define CS    33                 // skewed stride: bank = (s + lane) mod 32 -> 32 distinct banks
#define BLOCKS_PER_IMG 37        // 296 blocks total, 2 per SM
#define THREADS 1024
#define WARPS  (THREADS / 32)
#define GSTRIDE (BLOCKS_PER_IMG * WARPS * 4)   // 4736 pixels per sweep (HW % 4 == 0 -> full groups)

// Dynamic smem layout (floats): [0,8448) s_sum skewed, [8448,8704) s_pix, [8704,12800) stage
#define SMEM_FLOATS (S * CS + S + WARPS * 128)
#define SMEM_BYTES  (SMEM_FLOATS * 4)          // 51200

// Scratch (zero-initialized at module load; finalize restores zeros each call).
__device__ float g_sums[BATCH * S * C];
__device__ float g_zero[BATCH * S * C];   // zero-value corrections (rarely touched)
__device__ float g_pix [BATCH * S];

// ---------------------------------------------------------------------------
// Privatized scatter-reduce: 128-bit loads AND conflict-free atomics.
//   Load phase : warp = 4 consecutive pixels, lane (q=lane>>3, sub=lane&7)
//                loads float4 = channels [sub*4, sub*4+4) of pixel p0+q.
//                One LDG.128 instruction = 512B contiguous.
//   Transpose  : STS.128 into 512B warp-private staging, __syncwarp.
//   Atomic rds : round r: all 32 lanes process pixel p0+r. LDS.32 conflict-
//                free; atomicAdd(&s_sum[s*33+lane]) hits banks (s+lane)%32 =
//                all 32 distinct — conflict-free EVERY round (R4 had E[2.17x]
//                coset collisions; R5 fixed that but lost LDG.128 + MLP).
// ---------------------------------------------------------------------------
__global__ void __launch_bounds__(THREADS, 2)
seg_accum(const float* __restrict__ img, const int* __restrict__ slic) {
    extern __shared__ float sm[];
    float* s_sum = sm;                 // S*CS, skewed
    float* s_pix = sm + S * CS;        // S
    float* stage = sm + S * CS + S;    // WARPS * 128

    const int b    = blockIdx.y;
    const int warp = threadIdx.x >> 5;
    const int lane = threadIdx.x & 31;
    const int q    = lane >> 3;        // which of the 4 pixels this lane loads

    for (int i = threadIdx.x; i < S * CS; i += THREADS) s_sum[i] = 0.0f;
    if (threadIdx.x < S) s_pix[threadIdx.x] = 0.0f;
    __syncthreads();

    const float4* __restrict__ imgb4 = (const float4*)(img + (size_t)b * HW * C);
    const int*    __restrict__ slicb = slic + (size_t)b * HW;
    float* __restrict__ gz = g_zero + (size_t)b * S * C;

    float* st = stage + warp * 128;    // 512B warp-private staging

    for (int p0 = (blockIdx.x * WARPS + warp) * 4; p0 < HW; p0 += GSTRIDE) {
        const float4 v = imgb4[(size_t)p0 * 8 + lane];  // 512B contiguous/warp
        const int    s = slicb[p0 + q] - 1;             // 4 addrs, 1 sector

        ((float4*)st)[lane] = v;                        // STS.128
        __syncwarp();

        #pragma unroll
        for (int r = 0; r < 4; r++) {
            const int   sr  = __shfl_sync(0xffffffffu, s, r * 8);
            const float val = st[r * 32 + lane];        // LDS conflict-free
            atomicAdd(&s_sum[sr * CS + lane], val);     // 32 distinct banks
            if (val == 0.0f)                            // exact count_nonzero
                atomicAdd(&gz[sr * C + lane], 1.0f);
        }

        const int sq = __shfl_sync(0xffffffffu, s, (lane & 3) * 8);
        if (lane < 4) atomicAdd(&s_pix[sq], 1.0f);      // 1 instr / 4 pixels

        __syncwarp();   // LDS of this group before STS of the next
    }
    __syncthreads();

    // Flush block-private accumulators (de-skew). 296 blocks x 8448 lanes.
    float* __restrict__ gs = g_sums + (size_t)b * S * C;
    for (int i = threadIdx.x; i < S * C; i += THREADS) {
        const int s = i >> 5, c = i & 31;
        atomicAdd(&gs[i], s_sum[s * CS + c]);
    }
    if (threadIdx.x < S)
        atomicAdd(&g_pix[b * S + threadIdx.x], s_pix[threadIdx.x]);
}

// ---------------------------------------------------------------------------
// out = sum / (pixel_count - zero_count), then re-zero scratch for the next
// graph replay. g_pix read/write hazard confined to one warp (warp-wide load
// precedes the lane-0 store in program order).
// ---------------------------------------------------------------------------
__global__ void finalize(float* __restrict__ out) {
    int i = blockIdx.x * blockDim.x + threadIdx.x;
    if (i < BATCH * S * C) {
        float cnt = g_pix[i >> 5] - g_zero[i];
        out[i] = g_sums[i] / cnt;
        g_sums[i] = 0.0f;
        g_zero[i] = 0.0f;
        if ((i & 31) == 0) g_pix[i >> 5] = 0.0f;
    }
}

// ---------------------------------------------------------------------------
// Entry point (graph-capturable: kernel launches only; the attribute set is
// idempotent, not a stream op, and executes identically on every call).
// ---------------------------------------------------------------------------
extern "C" void kernel_launch(void* const* d_in, const int* in_sizes, int n_in,
                              void* d_out, int out_size) {
    const float* img  = (const float*)d_in[0];   // image, 67108864 f32
    const int*   slic = (const int*)  d_in[1];   // slic,   2097152 i32
    float*       out  = (float*)d_out;           // 65536 f32

    (void)in_sizes; (void)n_in; (void)out_size;

    cudaFuncSetAttribute(seg_accum,
                         cudaFuncAttributeMaxDynamicSharedMemorySize, SMEM_BYTES);

    dim3 grid(BLOCKS_PER_IMG, BATCH);
    seg_accum<<<grid, THREADS, SMEM_BYTES>>>(img, slic);

    finalize<<<(BATCH * S * C + 255) / 256, 256>>>(out);
}

// round 7
// speedup vs baseline: 1.3166x; 1.0024x over previous
#include <cuda_runtime.h>

// image [8,512,512,32] f32, slic [8,512,512,1] i32 in [1,256]
// out [8,256,32] f32 = segment_sum(image) / segment_count_nonzero(image) per channel.

#define BATCH 8
#define HW    (512*512)
#define C     32
#define S     256
#define CS    33                 // skewed stride: bank = (s + lane) mod 32 -> 32 distinct banks
#define BLOCKS_PER_IMG 37        // 296 blocks total, 2 per SM
#define THREADS 1024
#define WARPS  (THREADS / 32)
#define GSTRIDE (BLOCKS_PER_IMG * WARPS * 4)   // 4736 pixels per sweep (HW % 4 == 0 -> full groups)

// Dynamic smem layout (floats): [0,8448) s_sum skewed, [8448,8704) s_pix, [8704,12800) stage
#define SMEM_FLOATS (S * CS + S + WARPS * 128)
#define SMEM_BYTES  (SMEM_FLOATS * 4)          // 51200

// Scratch (zero-initialized at module load; finalize restores zeros each call).
__device__ float g_sums[BATCH * S * C];
__device__ float g_zero[BATCH * S * C];   // zero-value corrections (rarely touched)
__device__ float g_pix [BATCH * S];

// ---------------------------------------------------------------------------
// Privatized scatter-reduce: 128-bit loads AND conflict-free atomics.
//   Load phase : warp = 4 consecutive pixels, lane (q=lane>>3, sub=lane&7)
//                loads float4 = channels [sub*4, sub*4+4) of pixel p0+q.
//                One LDG.128 instruction = 512B contiguous.
//   Transpose  : STS.128 into 512B warp-private staging, __syncwarp.
//   Atomic rds : round r: all 32 lanes process pixel p0+r. LDS.32 conflict-
//                free; atomicAdd(&s_sum[s*33+lane]) hits banks (s+lane)%32 =
//                all 32 distinct — conflict-free EVERY round (R4 had E[2.17x]
//                coset collisions; R5 fixed that but lost LDG.128 + MLP).
// ---------------------------------------------------------------------------
__global__ void __launch_bounds__(THREADS, 2)
seg_accum(const float* __restrict__ img, const int* __restrict__ slic) {
    extern __shared__ float sm[];
    float* s_sum = sm;                 // S*CS, skewed
    float* s_pix = sm + S * CS;        // S
    float* stage = sm + S * CS + S;    // WARPS * 128

    const int b    = blockIdx.y;
    const int warp = threadIdx.x >> 5;
    const int lane = threadIdx.x & 31;
    const int q    = lane >> 3;        // which of the 4 pixels this lane loads

    for (int i = threadIdx.x; i < S * CS; i += THREADS) s_sum[i] = 0.0f;
    if (threadIdx.x < S) s_pix[threadIdx.x] = 0.0f;
    __syncthreads();

    const float4* __restrict__ imgb4 = (const float4*)(img + (size_t)b * HW * C);
    const int*    __restrict__ slicb = slic + (size_t)b * HW;
    float* __restrict__ gz = g_zero + (size_t)b * S * C;

    float* st = stage + warp * 128;    // 512B warp-private staging

    for (int p0 = (blockIdx.x * WARPS + warp) * 4; p0 < HW; p0 += GSTRIDE) {
        const float4 v = imgb4[(size_t)p0 * 8 + lane];  // 512B contiguous/warp
        const int    s = slicb[p0 + q] - 1;             // 4 addrs, 1 sector

        ((float4*)st)[lane] = v;                        // STS.128
        __syncwarp();

        #pragma unroll
        for (int r = 0; r < 4; r++) {
            const int   sr  = __shfl_sync(0xffffffffu, s, r * 8);
            const float val = st[r * 32 + lane];        // LDS conflict-free
            atomicAdd(&s_sum[sr * CS + lane], val);     // 32 distinct banks
            if (val == 0.0f)                            // exact count_nonzero
                atomicAdd(&gz[sr * C + lane], 1.0f);
        }

        const int sq = __shfl_sync(0xffffffffu, s, (lane & 3) * 8);
        if (lane < 4) atomicAdd(&s_pix[sq], 1.0f);      // 1 instr / 4 pixels

        __syncwarp();   // LDS of this group before STS of the next
    }
    __syncthreads();

    // Flush block-private accumulators (de-skew). 296 blocks x 8448 lanes.
    float* __restrict__ gs = g_sums + (size_t)b * S * C;
    for (int i = threadIdx.x; i < S * C; i += THREADS) {
        const int s = i >> 5, c = i & 31;
        atomicAdd(&gs[i], s_sum[s * CS + c]);
    }
    if (threadIdx.x < S)
        atomicAdd(&g_pix[b * S + threadIdx.x], s_pix[threadIdx.x]);
}

// ---------------------------------------------------------------------------
// out = sum / (pixel_count - zero_count), then re-zero scratch for the next
// graph replay. g_pix read/write hazard confined to one warp (warp-wide load
// precedes the lane-0 store in program order).
// ---------------------------------------------------------------------------
__global__ void finalize(float* __restrict__ out) {
    int i = blockIdx.x * blockDim.x + threadIdx.x;
    if (i < BATCH * S * C) {
        float cnt = g_pix[i >> 5] - g_zero[i];
        out[i] = g_sums[i] / cnt;
        g_sums[i] = 0.0f;
        g_zero[i] = 0.0f;
        if ((i & 31) == 0) g_pix[i >> 5] = 0.0f;
    }
}

// ---------------------------------------------------------------------------
// Entry point (graph-capturable: kernel launches only; the attribute set is
// idempotent, not a stream op, and executes identically on every call).
// ---------------------------------------------------------------------------
extern "C" void kernel_launch(void* const* d_in, const int* in_sizes, int n_in,
                              void* d_out, int out_size) {
    const float* img  = (const float*)d_in[0];   // image, 67108864 f32
    const int*   slic = (const int*)  d_in[1];   // slic,   2097152 i32
    float*       out  = (float*)d_out;           // 65536 f32

    (void)in_sizes; (void)n_in; (void)out_size;

    cudaFuncSetAttribute(seg_accum,
                         cudaFuncAttributeMaxDynamicSharedMemorySize, SMEM_BYTES);

    dim3 grid(BLOCKS_PER_IMG, BATCH);
    seg_accum<<<grid, THREADS, SMEM_BYTES>>>(img, slic);

    finalize<<<(BATCH * S * C + 255) / 256, 256>>>(out);
}